// round 1
// baseline (speedup 1.0000x reference)
#include <cuda_runtime.h>
#include <math.h>

// SafetyConstraint: per-row CBF evaluation.
// out[i] = clip( clip(h_grad . sdot, -100, 100) + 2*h, -20, 20 )
// h = smooth-min (logsumexp) of 6 barriers on pos/quat/vel.
// Gradient computed analytically (softmax weights of the LSE).

#define TPB 256

__global__ __launch_bounds__(TPB) void cbf_kernel(
    const float* __restrict__ state,   // [n, 18]
    const float* __restrict__ action,  // [n, 4]
    float* __restrict__ out,           // [n]
    int n)
{
    __shared__ float s[TPB * 18];

    const int blockBase = blockIdx.x * TPB;

    // ---- Stage state rows for this block into smem, fully coalesced ----
    if (blockBase + TPB <= n) {
        // Fast path: 1152 float4 loads (18432 bytes), stride-TPB coalesced.
        const float4* g4 = reinterpret_cast<const float4*>(state + (size_t)blockBase * 18);
        float4* s4 = reinterpret_cast<float4*>(s);
        #pragma unroll
        for (int i = threadIdx.x; i < TPB * 18 / 4; i += TPB) {
            s4[i] = g4[i];
        }
    } else {
        // Tail block: scalar guarded loads.
        int cnt = n - blockBase;
        if (cnt < 0) cnt = 0;
        for (int i = threadIdx.x; i < cnt * 18; i += TPB) {
            s[i] = state[(size_t)blockBase * 18 + i];
        }
    }
    __syncthreads();

    const int row = blockBase + threadIdx.x;
    if (row >= n) return;

    const float* r = s + threadIdx.x * 18;
    const float px = r[0],  py = r[1],  pz = r[2];
    const float qw = r[3],  qx = r[4],  qy = r[5],  qz = r[6];   // raw quat
    const float vx = r[7],  vy = r[8],  vz = r[9];
    const float wx = r[10], wy = r[11], wz = r[12];

    // action: only thrust needed; float4 load is fully coalesced (16B/lane).
    const float4 act = reinterpret_cast<const float4*>(action)[row];
    const float thrust = fminf(fmaxf(act.x, 0.0f), 0.35f);

    // ---- Quaternion normalization ----
    const float nsq = qw*qw + qx*qx + qy*qy + qz*qz;
    const float nrm = sqrtf(nsq);
    const float inv = 1.0f / (nrm + 1e-8f);
    const float uw = qw * inv, ux = qx * inv, uy = qy * inv, uz = qz * inv;

    // ---- Barriers ----
    float b0 = pz - 0.4f;                       // alt low
    float b1 = 1.6f - pz;                       // alt high
    float b2 = 1.0f - px * px;                  // pos x
    float b3 = 1.0f - py * py;                  // pos y
    float b4 = 0.16f - (vx*vx + vy*vy + vz*vz); // vel
    const float aq = fabsf(uw);
    const float qc = fminf(fmaxf(aq, 0.1f), 1.0f);
    float b5 = qc - 0.75f;                      // tilt

    // ---- Smooth min: h = -logsumexp(-beta*b)/beta ----
    const float BETA = 5.0f;
    float bmin = fminf(fminf(fminf(b0, b1), fminf(b2, b3)), fminf(b4, b5));
    const float e0 = expf(-BETA * (b0 - bmin));
    const float e1 = expf(-BETA * (b1 - bmin));
    const float e2 = expf(-BETA * (b2 - bmin));
    const float e3 = expf(-BETA * (b3 - bmin));
    const float e4 = expf(-BETA * (b4 - bmin));
    const float e5 = expf(-BETA * (b5 - bmin));
    const float S = e0 + e1 + e2 + e3 + e4 + e5;
    const float invS = 1.0f / S;
    const float h = bmin - logf(S) * (1.0f / BETA);

    // Softmax weights p_i = dh/db_i
    const float p0 = e0 * invS, p1 = e1 * invS, p2 = e2 * invS;
    const float p3 = e3 * invS, p4 = e4 * invS, p5 = e5 * invS;

    // ---- Analytical h_grad (nonzero only on pos, quat_raw, vel) ----
    // pos
    const float gpx = -2.0f * px * p2;
    const float gpy = -2.0f * py * p3;
    const float gpz = p0 - p1;
    // vel (only z component of vel_dot is nonzero, but pos-grad dots full vel)
    const float gvz = -2.0f * p4 * vz;
    // quat_raw: through clip(|uw|,0.1,1) and normalization
    const float active = (aq > 0.1f && aq < 1.0f) ? 1.0f : 0.0f;
    const float sgn = (uw >= 0.0f) ? 1.0f : -1.0f;
    const float coef = p5 * sgn * active;
    // d uw / d qraw_j = inv*delta_{0j} - uw*qraw_j*inv/nrm
    const float common = coef * uw * inv / nrm;
    const float gq0 = coef * inv - common * qw;
    const float gq1 = -common * qx;
    const float gq2 = -common * qy;
    const float gq3 = -common * qz;

    // ---- sdot pieces that matter ----
    // quat_dot (normalized quat x omega)
    const float qd0 = 0.5f * (-ux * wx - uy * wy - uz * wz);
    const float qd1 = 0.5f * ( uw * wx + uy * wz - uz * wy);
    const float qd2 = 0.5f * ( uw * wy + uz * wx - ux * wz);
    const float qd3 = 0.5f * ( uw * wz + ux * wy - uy * wx);
    // vel_dot z
    float R33 = 1.0f - 2.0f * (ux * ux + uy * uy);
    R33 = fminf(fmaxf(R33, -1.0f), 1.0f);
    const float az = thrust * R33 * (1.0f / 0.027f) - 9.81f;

    // ---- Lie derivative ----
    float lie = gpx * vx + gpy * vy + gpz * vz;      // grad_pos . vel
    lie += gq0 * qd0 + gq1 * qd1 + gq2 * qd2 + gq3 * qd3;  // grad_quat . quat_dot
    lie += gvz * az;                                  // grad_vel_z . vel_dot_z

    const float h_dot = fminf(fmaxf(lie, -100.0f), 100.0f);
    const float cbf = fminf(fmaxf(h_dot + 2.0f * h, -20.0f), 20.0f);

    out[row] = cbf;
}

extern "C" void kernel_launch(void* const* d_in, const int* in_sizes, int n_in,
                              void* d_out, int out_size)
{
    const float* state  = (const float*)d_in[0];
    const float* action = (const float*)d_in[1];
    float* out = (float*)d_out;

    const int n = out_size;  // one output per row
    const int grid = (n + TPB - 1) / TPB;
    cbf_kernel<<<grid, TPB>>>(state, action, out, n);
}

// round 2
// speedup vs baseline: 1.2232x; 1.2232x over previous
#include <cuda_runtime.h>
#include <math.h>

// SafetyConstraint CBF: out = clip(clip(grad(h).sdot,-100,100) + 2h, -20, 20)
// h = -logsumexp(-5*b)/5 over 6 barriers; gradient computed analytically.
//
// R2: 2 rows/thread, cp.async staging (9x16B per thread, exact trip count),
// to raise bytes-in-flight per SM and push DRAM toward peak.

#define TPB 256
#define ROWS_PER_BLOCK (TPB * 2)          // 512
#define STATE_F (ROWS_PER_BLOCK * 18)     // 9216 floats = 36864 B
#define VEC4 (STATE_F / 4)                // 2304 float4 -> 9 per thread

__device__ __forceinline__ float cbf_row(const float* __restrict__ r, float act0)
{
    const float px = r[0],  py = r[1],  pz = r[2];
    const float qw = r[3],  qx = r[4],  qy = r[5],  qz = r[6];
    const float vx = r[7],  vy = r[8],  vz = r[9];
    const float wx = r[10], wy = r[11], wz = r[12];

    const float thrust = fminf(fmaxf(act0, 0.0f), 0.35f);

    // quaternion normalization
    const float nsq = qw*qw + qx*qx + qy*qy + qz*qz;
    const float nrm = sqrtf(nsq);
    const float inv = 1.0f / (nrm + 1e-8f);
    const float uw = qw * inv, ux = qx * inv, uy = qy * inv, uz = qz * inv;

    // barriers
    const float b0 = pz - 0.4f;
    const float b1 = 1.6f - pz;
    const float b2 = 1.0f - px * px;
    const float b3 = 1.0f - py * py;
    const float b4 = 0.16f - (vx*vx + vy*vy + vz*vz);
    const float aq = fabsf(uw);
    const float qc = fminf(fmaxf(aq, 0.1f), 1.0f);
    const float b5 = qc - 0.75f;

    // smooth min (stable LSE)
    const float BETA = 5.0f;
    const float bmin = fminf(fminf(fminf(b0, b1), fminf(b2, b3)), fminf(b4, b5));
    const float e0 = __expf(-BETA * (b0 - bmin));
    const float e1 = __expf(-BETA * (b1 - bmin));
    const float e2 = __expf(-BETA * (b2 - bmin));
    const float e3 = __expf(-BETA * (b3 - bmin));
    const float e4 = __expf(-BETA * (b4 - bmin));
    const float e5 = __expf(-BETA * (b5 - bmin));
    const float S = e0 + e1 + e2 + e3 + e4 + e5;
    const float invS = 1.0f / S;
    const float h = bmin - __logf(S) * (1.0f / BETA);

    const float p0 = e0 * invS, p1 = e1 * invS, p2 = e2 * invS;
    const float p3 = e3 * invS, p4 = e4 * invS, p5 = e5 * invS;

    // analytical gradient pieces
    const float gpx = -2.0f * px * p2;
    const float gpy = -2.0f * py * p3;
    const float gpz = p0 - p1;
    const float gvz = -2.0f * p4 * vz;

    const float active = (aq > 0.1f && aq < 1.0f) ? 1.0f : 0.0f;
    const float sgn = (uw >= 0.0f) ? 1.0f : -1.0f;
    const float coef = p5 * sgn * active;
    const float common = coef * uw * inv / nrm;
    const float gq0 = coef * inv - common * qw;
    const float gq1 = -common * qx;
    const float gq2 = -common * qy;
    const float gq3 = -common * qz;

    // sdot pieces with nonzero gradient
    const float qd0 = 0.5f * (-ux * wx - uy * wy - uz * wz);
    const float qd1 = 0.5f * ( uw * wx + uy * wz - uz * wy);
    const float qd2 = 0.5f * ( uw * wy + uz * wx - ux * wz);
    const float qd3 = 0.5f * ( uw * wz + ux * wy - uy * wx);
    float R33 = 1.0f - 2.0f * (ux * ux + uy * uy);
    R33 = fminf(fmaxf(R33, -1.0f), 1.0f);
    const float az = thrust * R33 * (1.0f / 0.027f) - 9.81f;

    float lie = gpx * vx + gpy * vy + gpz * vz;
    lie += gq0 * qd0 + gq1 * qd1 + gq2 * qd2 + gq3 * qd3;
    lie += gvz * az;

    const float h_dot = fminf(fmaxf(lie, -100.0f), 100.0f);
    return fminf(fmaxf(h_dot + 2.0f * h, -20.0f), 20.0f);
}

__global__ __launch_bounds__(TPB) void cbf_kernel(
    const float* __restrict__ state,   // [n, 18]
    const float* __restrict__ action,  // [n, 4]
    float* __restrict__ out,           // [n]
    int n)
{
    __shared__ float s[STATE_F];

    const int blockBase = blockIdx.x * ROWS_PER_BLOCK;

    if (blockBase + ROWS_PER_BLOCK <= n) {
        // ---- Fast path: cp.async staging, 9 x 16B per thread, exact ----
        const float4* g4 = reinterpret_cast<const float4*>(state + (size_t)blockBase * 18);
        unsigned smem_base = (unsigned)__cvta_generic_to_shared(s);
        #pragma unroll
        for (int k = 0; k < 9; k++) {
            int i = threadIdx.x + k * TPB;
            unsigned dst = smem_base + i * 16u;
            const float4* src = g4 + i;
            asm volatile("cp.async.cg.shared.global [%0], [%1], 16;\n"
                         :: "r"(dst), "l"(src));
        }
        asm volatile("cp.async.commit_group;\n" ::: "memory");

        // overlap: fetch both action words while staging is in flight
        const int row0 = blockBase + threadIdx.x;
        const int row1 = row0 + TPB;
        const float4 act0 = reinterpret_cast<const float4*>(action)[row0];
        const float4 act1 = reinterpret_cast<const float4*>(action)[row1];

        asm volatile("cp.async.wait_group 0;\n" ::: "memory");
        __syncthreads();

        const float* r0 = s + threadIdx.x * 18;
        const float* r1 = s + (threadIdx.x + TPB) * 18;

        out[row0] = cbf_row(r0, act0.x);
        out[row1] = cbf_row(r1, act1.x);
    } else {
        // ---- Tail path: guarded scalar staging + compute ----
        int cnt = n - blockBase;
        if (cnt < 0) cnt = 0;
        for (int i = threadIdx.x; i < cnt * 18; i += TPB) {
            s[i] = state[(size_t)blockBase * 18 + i];
        }
        __syncthreads();
        for (int l = threadIdx.x; l < cnt; l += TPB) {
            const int row = blockBase + l;
            const float a0 = action[(size_t)row * 4];
            out[row] = cbf_row(s + l * 18, a0);
        }
    }
}

extern "C" void kernel_launch(void* const* d_in, const int* in_sizes, int n_in,
                              void* d_out, int out_size)
{
    const float* state  = (const float*)d_in[0];
    const float* action = (const float*)d_in[1];
    float* out = (float*)d_out;

    const int n = out_size;
    const int grid = (n + ROWS_PER_BLOCK - 1) / ROWS_PER_BLOCK;
    cbf_kernel<<<grid, TPB>>>(state, action, out, n);
}